// round 1
// baseline (speedup 1.0000x reference)
#include <cuda_runtime.h>
#include <math.h>

#define N_NODES 100000
#define N_EDGES 3200000
#define MAXW 12

// Scratch: ping-pong node-feature buffers (max width 12)
__device__ float g_bufA[N_NODES * MAXW];   // mm output s
__device__ float g_bufB[N_NODES * MAXW];   // aggregation target

// ---------------------------------------------------------------------------
// Layer-1 dense MM: s[100000,12] = x[100000,512] @ W1[512,12]
// warp-per-row, W1 staged in shared with pad-13 to kill bank conflicts.
// ---------------------------------------------------------------------------
__global__ void mm1_kernel(const float* __restrict__ x,
                           const float* __restrict__ W,
                           float* __restrict__ out) {
    __shared__ float sW[512 * 13];
    for (int i = threadIdx.x; i < 512 * 12; i += blockDim.x) {
        int k = i / 12, j = i % 12;
        sW[k * 13 + j] = W[i];
    }
    __syncthreads();

    int warp = (blockIdx.x * blockDim.x + threadIdx.x) >> 5;
    int lane = threadIdx.x & 31;
    if (warp >= N_NODES) return;

    const float* xr = x + (size_t)warp * 512;
    float acc[12];
#pragma unroll
    for (int j = 0; j < 12; j++) acc[j] = 0.f;

    // each lane handles k = lane, lane+32, ... (coalesced x reads)
#pragma unroll 4
    for (int k = lane; k < 512; k += 32) {
        float xv = xr[k];
#pragma unroll
        for (int j = 0; j < 12; j++) acc[j] = fmaf(xv, sW[k * 13 + j], acc[j]);
    }
#pragma unroll
    for (int j = 0; j < 12; j++) {
#pragma unroll
        for (int o = 16; o > 0; o >>= 1)
            acc[j] += __shfl_down_sync(0xffffffffu, acc[j], o);
    }
    if (lane == 0) {
        float* o = out + (size_t)warp * 12;
#pragma unroll
        for (int j = 0; j < 12; j++) o[j] = acc[j];
    }
}

// ---------------------------------------------------------------------------
// Small dense MM for layers 2..6. Reads previous layer's aggregation,
// applies (bias + activation) fused, then multiplies by W.
// ACT: 0=identity, 1=relu, 2=tanhshrink
// ---------------------------------------------------------------------------
template <int DIN, int DOUT, int ACT>
__global__ void small_mm_kernel(const float* __restrict__ in,
                                const float* __restrict__ W,
                                const float* __restrict__ bprev,
                                float* __restrict__ out) {
    __shared__ float sW[DIN * DOUT];
    __shared__ float sb[DIN];
    for (int i = threadIdx.x; i < DIN * DOUT; i += blockDim.x) sW[i] = W[i];
    if (threadIdx.x < DIN) sb[threadIdx.x] = bprev[threadIdx.x];
    __syncthreads();

    int row = blockIdx.x * blockDim.x + threadIdx.x;
    if (row >= N_NODES) return;

    float h[DIN];
#pragma unroll
    for (int k = 0; k < DIN; k++) {
        float v = in[(size_t)row * DIN + k] + sb[k];
        if (ACT == 1) v = fmaxf(v, 0.f);
        else if (ACT == 2) v = v - tanhf(v);
        h[k] = v;
    }
#pragma unroll
    for (int j = 0; j < DOUT; j++) {
        float a = 0.f;
#pragma unroll
        for (int k = 0; k < DIN; k++) a = fmaf(h[k], sW[k * DOUT + j], a);
        out[(size_t)row * DOUT + j] = a;
    }
}

// ---------------------------------------------------------------------------
// Edge scatter: agg[dst, :] += edge_val * s[src, :]   (atomicAdd / REDG)
// One thread per (edge, feature) pair.
// ---------------------------------------------------------------------------
template <int D>
__global__ void scatter_kernel(const float* __restrict__ s,
                               const float* __restrict__ ev,
                               const int* __restrict__ src,
                               const int* __restrict__ dst,
                               float* __restrict__ agg) {
    long long idx = (long long)blockIdx.x * blockDim.x + threadIdx.x;
    const long long total = (long long)N_EDGES * D;
    if (idx >= total) return;
    int e = (int)(idx / D);
    int j = (int)(idx % D);
    float v = ev[e] * s[(size_t)src[e] * D + j];
    atomicAdd(&agg[(size_t)dst[e] * D + j], v);
}

__global__ void zero_kernel(float* __restrict__ p, int n) {
    int i = blockIdx.x * blockDim.x + threadIdx.x;
    if (i < n) p[i] = 0.f;
}

// final: out += b6 (broadcast over rows, width 7)
__global__ void bias_final_kernel(float* __restrict__ out,
                                  const float* __restrict__ b) {
    int i = blockIdx.x * blockDim.x + threadIdx.x;
    if (i < N_NODES * 7) out[i] += b[i % 7];
}

// ---------------------------------------------------------------------------
// Launch
// ---------------------------------------------------------------------------
extern "C" void kernel_launch(void* const* d_in, const int* in_sizes, int n_in,
                              void* d_out, int out_size) {
    const float* x = nullptr;
    const float* ev = nullptr;
    const int* esrc = nullptr;
    const int* edst = nullptr;
    const float* W[6] = {0};
    const float* b[6] = {0};
    const int wsz[6] = {512 * 12, 12 * 10, 10 * 8, 8 * 6, 6 * 4, 4 * 7};
    const int bsz[6] = {12, 10, 8, 6, 4, 7};

    int edgeSeen = 0;
    for (int i = 0; i < n_in; i++) {
        int sz = in_sizes[i];
        if (sz == N_NODES * 512) {
            x = (const float*)d_in[i];
        } else if (sz == N_EDGES) {
            if (edgeSeen == 0) ev = (const float*)d_in[i];
            else if (edgeSeen == 1) esrc = (const int*)d_in[i];
            else edst = (const int*)d_in[i];
            edgeSeen++;
        } else {
            for (int j = 0; j < 6; j++) {
                if (sz == wsz[j]) W[j] = (const float*)d_in[i];
                else if (sz == bsz[j]) b[j] = (const float*)d_in[i];
            }
        }
    }

    float* bufA = nullptr;
    float* bufB = nullptr;
    cudaGetSymbolAddress((void**)&bufA, g_bufA);
    cudaGetSymbolAddress((void**)&bufB, g_bufB);
    float* out = (float*)d_out;

    const int TB = 256;
    auto blocks = [](long long n, int tb) { return (int)((n + tb - 1) / tb); };

    // ---- Layer 1: s = x @ W1 ; agg = scatter(s) ----
    mm1_kernel<<<blocks((long long)N_NODES * 32, TB), TB>>>(x, W[0], bufA);
    zero_kernel<<<blocks(N_NODES * 12, TB), TB>>>(bufB, N_NODES * 12);
    scatter_kernel<12><<<blocks((long long)N_EDGES * 12, TB), TB>>>(bufA, ev, esrc, edst, bufB);

    // ---- Layer 2: in = (agg1 + b1), identity ----
    small_mm_kernel<12, 10, 0><<<blocks(N_NODES, TB), TB>>>(bufB, W[1], b[0], bufA);
    zero_kernel<<<blocks(N_NODES * 10, TB), TB>>>(bufB, N_NODES * 10);
    scatter_kernel<10><<<blocks((long long)N_EDGES * 10, TB), TB>>>(bufA, ev, esrc, edst, bufB);

    // ---- Layer 3: in = relu(agg2 + b2) ----
    small_mm_kernel<10, 8, 1><<<blocks(N_NODES, TB), TB>>>(bufB, W[2], b[1], bufA);
    zero_kernel<<<blocks(N_NODES * 8, TB), TB>>>(bufB, N_NODES * 8);
    scatter_kernel<8><<<blocks((long long)N_EDGES * 8, TB), TB>>>(bufA, ev, esrc, edst, bufB);

    // ---- Layer 4: in = tanhshrink(agg3 + b3) ----
    small_mm_kernel<8, 6, 2><<<blocks(N_NODES, TB), TB>>>(bufB, W[3], b[2], bufA);
    zero_kernel<<<blocks(N_NODES * 6, TB), TB>>>(bufB, N_NODES * 6);
    scatter_kernel<6><<<blocks((long long)N_EDGES * 6, TB), TB>>>(bufA, ev, esrc, edst, bufB);

    // ---- Layer 5: in = tanhshrink(agg4 + b4) ----
    small_mm_kernel<6, 4, 2><<<blocks(N_NODES, TB), TB>>>(bufB, W[4], b[3], bufA);
    zero_kernel<<<blocks(N_NODES * 4, TB), TB>>>(bufB, N_NODES * 4);
    scatter_kernel<4><<<blocks((long long)N_EDGES * 4, TB), TB>>>(bufA, ev, esrc, edst, bufB);

    // ---- Layer 6: in = (agg5 + b5), identity; scatter straight into d_out ----
    small_mm_kernel<4, 7, 0><<<blocks(N_NODES, TB), TB>>>(bufB, W[5], b[4], bufA);
    zero_kernel<<<blocks(N_NODES * 7, TB), TB>>>(out, N_NODES * 7);
    scatter_kernel<7><<<blocks((long long)N_EDGES * 7, TB), TB>>>(bufA, ev, esrc, edst, out);
    bias_final_kernel<<<blocks(N_NODES * 7, TB), TB>>>(out, b[5]);

    (void)out_size;
}

// round 2
// speedup vs baseline: 1.2020x; 1.2020x over previous
#include <cuda_runtime.h>
#include <math.h>

#define N_NODES 100000
#define N_EDGES 3200000
#define MAXW 12

// Scratch: ping-pong node-feature buffers (max row stride 12 floats)
__device__ float g_bufA[(size_t)N_NODES * MAXW];   // mm output s (padded stride)
__device__ float g_bufB[(size_t)N_NODES * MAXW];   // aggregation target (padded stride)

// ---------------------------------------------------------------------------
// Vector global reductions (sm_90+)
// ---------------------------------------------------------------------------
__device__ __forceinline__ void red_add_v4(float* p, float4 v) {
    asm volatile("red.global.add.v4.f32 [%0], {%1, %2, %3, %4};"
                 :: "l"(p), "f"(v.x), "f"(v.y), "f"(v.z), "f"(v.w) : "memory");
}
__device__ __forceinline__ void red_add_v2(float* p, float a, float b) {
    asm volatile("red.global.add.v2.f32 [%0], {%1, %2};"
                 :: "l"(p), "f"(a), "f"(b) : "memory");
}
__device__ __forceinline__ void red_add_f(float* p, float a) {
    asm volatile("red.global.add.f32 [%0], %1;"
                 :: "l"(p), "f"(a) : "memory");
}

// ---------------------------------------------------------------------------
// Layer-1 dense MM: s[100000,12] = x[100000,512] @ W1[512,12]
// warp-per-row, float4 x loads, W1 staged in shared (pad 13).
// ---------------------------------------------------------------------------
__global__ void mm1_kernel(const float* __restrict__ x,
                           const float* __restrict__ W,
                           float* __restrict__ out) {
    __shared__ float sW[512 * 13];
    for (int i = threadIdx.x; i < 512 * 12; i += blockDim.x) {
        int k = i / 12, j = i % 12;
        sW[k * 13 + j] = W[i];
    }
    __syncthreads();

    int warp = (blockIdx.x * blockDim.x + threadIdx.x) >> 5;
    int lane = threadIdx.x & 31;
    if (warp >= N_NODES) return;

    const float4* xr = reinterpret_cast<const float4*>(x + (size_t)warp * 512);
    float acc[12];
#pragma unroll
    for (int j = 0; j < 12; j++) acc[j] = 0.f;

    // 512 floats = 128 float4; each lane takes 4 float4 chunks
#pragma unroll
    for (int it = 0; it < 4; it++) {
        int k4 = it * 32 + lane;          // float4 index
        float4 xv = xr[k4];
        int k = k4 * 4;
#pragma unroll
        for (int j = 0; j < 12; j++) {
            acc[j] = fmaf(xv.x, sW[(k + 0) * 13 + j], acc[j]);
            acc[j] = fmaf(xv.y, sW[(k + 1) * 13 + j], acc[j]);
            acc[j] = fmaf(xv.z, sW[(k + 2) * 13 + j], acc[j]);
            acc[j] = fmaf(xv.w, sW[(k + 3) * 13 + j], acc[j]);
        }
    }
#pragma unroll
    for (int j = 0; j < 12; j++) {
#pragma unroll
        for (int o = 16; o > 0; o >>= 1)
            acc[j] += __shfl_down_sync(0xffffffffu, acc[j], o);
    }
    if (lane == 0) {
        float* o = out + (size_t)warp * 12;
#pragma unroll
        for (int j = 0; j < 12; j++) o[j] = acc[j];
    }
}

// ---------------------------------------------------------------------------
// Small dense MM for layers 2..6 with padded strides.
// in: stride SIN, logical width DIN. out: stride SOUT, logical width DOUT.
// ACT applied to (in + bias_prev): 0=identity, 1=relu, 2=tanhshrink
// ---------------------------------------------------------------------------
template <int DIN, int SIN, int DOUT, int SOUT, int ACT>
__global__ void small_mm_kernel(const float* __restrict__ in,
                                const float* __restrict__ W,
                                const float* __restrict__ bprev,
                                float* __restrict__ out) {
    __shared__ float sW[DIN * DOUT];
    __shared__ float sb[DIN];
    for (int i = threadIdx.x; i < DIN * DOUT; i += blockDim.x) sW[i] = W[i];
    if (threadIdx.x < DIN) sb[threadIdx.x] = bprev[threadIdx.x];
    __syncthreads();

    int row = blockIdx.x * blockDim.x + threadIdx.x;
    if (row >= N_NODES) return;

    float h[DIN];
    const float* ir = in + (size_t)row * SIN;
#pragma unroll
    for (int k = 0; k < DIN; k++) {
        float v = ir[k] + sb[k];
        if (ACT == 1) v = fmaxf(v, 0.f);
        else if (ACT == 2) v = v - tanhf(v);
        h[k] = v;
    }
    float* o = out + (size_t)row * SOUT;
#pragma unroll
    for (int j = 0; j < DOUT; j++) {
        float a = 0.f;
#pragma unroll
        for (int k = 0; k < DIN; k++) a = fmaf(h[k], sW[k * DOUT + j], a);
        o[j] = a;
    }
}

// ---------------------------------------------------------------------------
// Edge scatter, one THREAD PER EDGE, vector red.global for the whole row:
//   agg[dst, 0:D] += edge_val * s[src, 0:D]   (row stride S, S % 4 == 0)
// ---------------------------------------------------------------------------
template <int D, int S>
__global__ void scatter_vec_kernel(const float* __restrict__ s,
                                   const float* __restrict__ ev,
                                   const int* __restrict__ src,
                                   const int* __restrict__ dst,
                                   float* __restrict__ agg) {
    int e = blockIdx.x * blockDim.x + threadIdx.x;
    if (e >= N_EDGES) return;
    float v = ev[e];
    const float* srow = s + (size_t)src[e] * S;
    float* arow = agg + (size_t)dst[e] * S;

    int j = 0;
#pragma unroll
    for (; j + 4 <= D; j += 4) {
        float4 t = *reinterpret_cast<const float4*>(srow + j);
        t.x *= v; t.y *= v; t.z *= v; t.w *= v;
        red_add_v4(arow + j, t);
    }
    if (D - j >= 2) {
        float2 t = *reinterpret_cast<const float2*>(srow + j);
        red_add_v2(arow + j, t.x * v, t.y * v);
        j += 2;
    }
    if (j < D) red_add_f(arow + j, srow[j] * v);
}

// final: out[r,0:7] = agg[r*8 + 0:7] + b6
__global__ void finalize_kernel(const float* __restrict__ agg,
                                const float* __restrict__ b,
                                float* __restrict__ out) {
    int i = blockIdx.x * blockDim.x + threadIdx.x;
    if (i >= N_NODES * 7) return;
    int r = i / 7, j = i % 7;
    out[i] = agg[(size_t)r * 8 + j] + b[j];
}

// ---------------------------------------------------------------------------
// Launch
// ---------------------------------------------------------------------------
extern "C" void kernel_launch(void* const* d_in, const int* in_sizes, int n_in,
                              void* d_out, int out_size) {
    const float* x = nullptr;
    const float* ev = nullptr;
    const int* esrc = nullptr;
    const int* edst = nullptr;
    const float* W[6] = {0};
    const float* b[6] = {0};
    const int wsz[6] = {512 * 12, 12 * 10, 10 * 8, 8 * 6, 6 * 4, 4 * 7};
    const int bsz[6] = {12, 10, 8, 6, 4, 7};

    int edgeSeen = 0;
    for (int i = 0; i < n_in; i++) {
        int sz = in_sizes[i];
        if (sz == N_NODES * 512) {
            x = (const float*)d_in[i];
        } else if (sz == N_EDGES) {
            if (edgeSeen == 0) ev = (const float*)d_in[i];
            else if (edgeSeen == 1) esrc = (const int*)d_in[i];
            else edst = (const int*)d_in[i];
            edgeSeen++;
        } else {
            for (int j = 0; j < 6; j++) {
                if (sz == wsz[j]) W[j] = (const float*)d_in[i];
                else if (sz == bsz[j]) b[j] = (const float*)d_in[i];
            }
        }
    }

    float* bufA = nullptr;
    float* bufB = nullptr;
    cudaGetSymbolAddress((void**)&bufA, g_bufA);
    cudaGetSymbolAddress((void**)&bufB, g_bufB);
    float* out = (float*)d_out;

    const int TB = 256;
    auto blocks = [](long long n, int tb) { return (int)((n + tb - 1) / tb); };
    const int EB = blocks(N_EDGES, TB);
    const int NB = blocks(N_NODES, TB);

    // Strides (floats, multiple of 4): layer outputs 12,10,8,6,4,7
    // S: 12, 12, 8, 8, 4, 8

    // ---- Layer 1: s = x @ W1 (width 12 / stride 12) ----
    mm1_kernel<<<blocks((long long)N_NODES * 32, TB), TB>>>(x, W[0], bufA);
    cudaMemsetAsync(bufB, 0, (size_t)N_NODES * 12 * sizeof(float));
    scatter_vec_kernel<12, 12><<<EB, TB>>>(bufA, ev, esrc, edst, bufB);

    // ---- Layer 2: identity(agg1 + b1) @ W2 (10 wide, stride 12) ----
    small_mm_kernel<12, 12, 10, 12, 0><<<NB, TB>>>(bufB, W[1], b[0], bufA);
    cudaMemsetAsync(bufB, 0, (size_t)N_NODES * 12 * sizeof(float));
    scatter_vec_kernel<10, 12><<<EB, TB>>>(bufA, ev, esrc, edst, bufB);

    // ---- Layer 3: relu(agg2 + b2) @ W3 (8 wide, stride 8) ----
    small_mm_kernel<10, 12, 8, 8, 1><<<NB, TB>>>(bufB, W[2], b[1], bufA);
    cudaMemsetAsync(bufB, 0, (size_t)N_NODES * 8 * sizeof(float));
    scatter_vec_kernel<8, 8><<<EB, TB>>>(bufA, ev, esrc, edst, bufB);

    // ---- Layer 4: tanhshrink(agg3 + b3) @ W4 (6 wide, stride 8) ----
    small_mm_kernel<8, 8, 6, 8, 2><<<NB, TB>>>(bufB, W[3], b[2], bufA);
    cudaMemsetAsync(bufB, 0, (size_t)N_NODES * 8 * sizeof(float));
    scatter_vec_kernel<6, 8><<<EB, TB>>>(bufA, ev, esrc, edst, bufB);

    // ---- Layer 5: tanhshrink(agg4 + b4) @ W5 (4 wide, stride 4) ----
    small_mm_kernel<6, 8, 4, 4, 2><<<NB, TB>>>(bufB, W[4], b[3], bufA);
    cudaMemsetAsync(bufB, 0, (size_t)N_NODES * 4 * sizeof(float));
    scatter_vec_kernel<4, 4><<<EB, TB>>>(bufA, ev, esrc, edst, bufB);

    // ---- Layer 6: identity(agg5 + b5) @ W6 (7 wide, stride 8), scatter to scratch ----
    small_mm_kernel<4, 4, 7, 8, 0><<<NB, TB>>>(bufB, W[5], b[4], bufA);
    cudaMemsetAsync(bufB, 0, (size_t)N_NODES * 8 * sizeof(float));
    scatter_vec_kernel<7, 8><<<EB, TB>>>(bufA, ev, esrc, edst, bufB);

    // ---- finalize: out = agg6 + b6 ----
    finalize_kernel<<<blocks((long long)N_NODES * 7, TB), TB>>>(bufB, b[5], out);

    (void)out_size;
}